// round 10
// baseline (speedup 1.0000x reference)
#include <cuda_runtime.h>

// Two-kernel split:
//  K1: gather/mean -> g_comb[4096][256]  (~23MB traffic, ~5us)
//  K2: pure per-sample matvec stream of weight (512MB) with comb read from
//      g_comb (L2-hot). No dependent gather chain inside the streaming
//      kernel: each warp's ramp is a single float2 load.
// Shapes: features [100000,128] f32, weight [4096,256,128] f32,
//         nodes [4096] i32, neigh_idx [4096,10] i32, out [4096,128] f32.

#define FEAT 128
#define EMBED 128
#define TWO_FEAT 256
#define NUM_SAMPLE 10
#define BATCH_MAX 4096

__device__ float g_comb[BATCH_MAX * TWO_FEAT];   // 4MB scratch

// ---------------- K1: build combined vectors ----------------
__global__ __launch_bounds__(128)
void gather_kernel(const float* __restrict__ features,
                   const int*   __restrict__ nodes,
                   const int*   __restrict__ neigh)
{
    const int b = blockIdx.x;
    const int t = threadIdx.x;          // 0..127, owns feature dim t

    const int node = __ldg(&nodes[b]);
    const float self_f = __ldg(&features[(size_t)node * FEAT + t]);

    float msum = 0.0f;
    #pragma unroll
    for (int j = 0; j < NUM_SAMPLE; ++j) {
        const int nb = __ldg(&neigh[b * NUM_SAMPLE + j]);
        msum += __ldg(&features[(size_t)nb * FEAT + t]);
    }

    g_comb[b * TWO_FEAT + t]        = self_f;
    g_comb[b * TWO_FEAT + FEAT + t] = msum * (1.0f / NUM_SAMPLE);
}

// ---------------- K2: pure weight stream ----------------
__global__ __launch_bounds__(128, 10)
void matvec_kernel(const float* __restrict__ weight,
                   float*       __restrict__ out)
{
    __shared__ float comb[TWO_FEAT];
    __shared__ float part[4][EMBED];

    const int b = blockIdx.x;
    const int t = threadIdx.x;
    const int warp = t >> 5;
    const int lane = t & 31;

    // warp w owns comb[64w..64w+64): one float2 per lane, L2-hot, then stream.
    {
        const float2 c = *reinterpret_cast<const float2*>(
            &g_comb[b * TWO_FEAT + warp * 64 + lane * 2]);
        *reinterpret_cast<float2*>(&comb[warp * 64 + lane * 2]) = c;
        __syncwarp();
    }

    // warp w streams rows [64w, 64w+64); lane covers e = 4*lane..4*lane+3.
    const float4* __restrict__ Wb =
        reinterpret_cast<const float4*>(weight + (size_t)b * TWO_FEAT * EMBED);
    const int i0 = warp * 64;

    float4 accA = make_float4(0.f, 0.f, 0.f, 0.f);
    float4 accB = make_float4(0.f, 0.f, 0.f, 0.f);

    #pragma unroll 8
    for (int k = 0; k < 64; k += 2) {
        const float  cA = comb[i0 + k];
        const float  cB = comb[i0 + k + 1];
        const float4 wA = __ldcs(&Wb[(size_t)(i0 + k)     * (EMBED / 4) + lane]);
        const float4 wB = __ldcs(&Wb[(size_t)(i0 + k + 1) * (EMBED / 4) + lane]);
        accA.x = fmaf(cA, wA.x, accA.x); accA.y = fmaf(cA, wA.y, accA.y);
        accA.z = fmaf(cA, wA.z, accA.z); accA.w = fmaf(cA, wA.w, accA.w);
        accB.x = fmaf(cB, wB.x, accB.x); accB.y = fmaf(cB, wB.y, accB.y);
        accB.z = fmaf(cB, wB.z, accB.z); accB.w = fmaf(cB, wB.w, accB.w);
    }

    float4 acc;
    acc.x = accA.x + accB.x;
    acc.y = accA.y + accB.y;
    acc.z = accA.z + accB.z;
    acc.w = accA.w + accB.w;

    reinterpret_cast<float4*>(&part[warp][0])[lane] = acc;
    __syncthreads();

    // reduce 4 warps, relu, store (coalesced 512B)
    const float v = part[0][t] + part[1][t] + part[2][t] + part[3][t];
    out[(size_t)b * EMBED + t] = fmaxf(v, 0.0f);
}

extern "C" void kernel_launch(void* const* d_in, const int* in_sizes, int n_in,
                              void* d_out, int out_size)
{
    const float* features = (const float*)d_in[0];
    const float* weight   = (const float*)d_in[1];
    const int*   nodes    = (const int*)d_in[2];
    const int*   neigh    = (const int*)d_in[3];
    float*       out      = (float*)d_out;

    const int batch = in_sizes[2];      // 4096 (nodes element count)

    gather_kernel<<<batch, 128>>>(features, nodes, neigh);
    matvec_kernel<<<batch, 128>>>(weight, out);
}

// round 11
// speedup vs baseline: 1.0366x; 1.0366x over previous
#include <cuda_runtime.h>

// Encoder: out[b,e] = relu( sum_i combined[b,i] * weight[b,i,e] )
// combined = [ features[nodes[b]] , mean_j features[neigh_idx[b,j]] ]  (256 dims)
// Shapes: features [100000,128] f32, weight [4096,256,128] f32,
//         nodes [4096] i32, neigh_idx [4096,10] i32, out [4096,128] f32.
//
// Final form: DRAM-bound streaming kernel at the measured ~6.4-6.5TB/s
// platform ceiling (confirmed by a pure-stream split kernel in R10).
//  - warp-local gather: warp w builds exactly the comb slice it consumes,
//    so no block barrier between gather and stream (warps 0/1 start the
//    weight stream after a single row fetch).
//  - weight streamed with __ldcs float4 rows (512B/warp/request).
//  - 48 regs, 10 CTAs/SM; fully unrolled stream loop.

#define FEAT 128
#define EMBED 128
#define TWO_FEAT 256
#define NUM_SAMPLE 10

__global__ __launch_bounds__(128, 10)
void encoder_kernel(const float* __restrict__ features,
                    const float* __restrict__ weight,
                    const int*   __restrict__ nodes,
                    const int*   __restrict__ neigh,
                    float*       __restrict__ out)
{
    __shared__ float comb[TWO_FEAT];
    __shared__ float part[4][EMBED];

    const int b = blockIdx.x;
    const int t = threadIdx.x;          // 0..127
    const int warp = t >> 5;
    const int lane = t & 31;

    // ---- Phase 1 (warp-local): warp w builds comb[64w .. 64w+64).
    //   warp 0 -> self dims [0,64)     warp 1 -> self dims [64,128)
    //   warp 2 -> mean dims [0,64)     warp 3 -> mean dims [64,128)
    {
        const int dim0 = (warp & 1) * 64 + lane * 2;
        float2 v;
        if (warp < 2) {
            const int node = __ldg(&nodes[b]);
            v = *reinterpret_cast<const float2*>(&features[(size_t)node * FEAT + dim0]);
        } else {
            float sx = 0.0f, sy = 0.0f;
            #pragma unroll
            for (int j = 0; j < NUM_SAMPLE; ++j) {
                const int nb = __ldg(&neigh[b * NUM_SAMPLE + j]);
                const float2 f = *reinterpret_cast<const float2*>(
                    &features[(size_t)nb * FEAT + dim0]);
                sx += f.x; sy += f.y;
            }
            v.x = sx * (1.0f / NUM_SAMPLE);
            v.y = sy * (1.0f / NUM_SAMPLE);
        }
        *reinterpret_cast<float2*>(&comb[warp * 64 + lane * 2]) = v;
        __syncwarp();
    }

    // ---- Phase 2: per-sample matvec, streaming weight[b] (128 KB/CTA).
    // warp w handles rows [w*64, w*64+64) == the comb slice it wrote.
    // lane covers e = 4*lane..4*lane+3. __ldcs: weight is single-use.
    const float4* __restrict__ Wb =
        reinterpret_cast<const float4*>(weight + (size_t)b * TWO_FEAT * EMBED);
    const int i0 = warp * 64;

    float4 accA = make_float4(0.f, 0.f, 0.f, 0.f);
    float4 accB = make_float4(0.f, 0.f, 0.f, 0.f);

    #pragma unroll
    for (int k = 0; k < 64; k += 2) {
        const float  cA = comb[i0 + k];
        const float  cB = comb[i0 + k + 1];
        const float4 wA = __ldcs(&Wb[(size_t)(i0 + k)     * (EMBED / 4) + lane]);
        const float4 wB = __ldcs(&Wb[(size_t)(i0 + k + 1) * (EMBED / 4) + lane]);
        accA.x = fmaf(cA, wA.x, accA.x); accA.y = fmaf(cA, wA.y, accA.y);
        accA.z = fmaf(cA, wA.z, accA.z); accA.w = fmaf(cA, wA.w, accA.w);
        accB.x = fmaf(cB, wB.x, accB.x); accB.y = fmaf(cB, wB.y, accB.y);
        accB.z = fmaf(cB, wB.z, accB.z); accB.w = fmaf(cB, wB.w, accB.w);
    }

    float4 acc;
    acc.x = accA.x + accB.x;
    acc.y = accA.y + accB.y;
    acc.z = accA.z + accB.z;
    acc.w = accA.w + accB.w;

    // stash per-warp partials
    reinterpret_cast<float4*>(&part[warp][0])[lane] = acc;
    __syncthreads();

    // ---- reduce 4 warps, relu, store (coalesced 512B)
    const float v = part[0][t] + part[1][t] + part[2][t] + part[3][t];
    out[(size_t)b * EMBED + t] = fmaxf(v, 0.0f);
}

extern "C" void kernel_launch(void* const* d_in, const int* in_sizes, int n_in,
                              void* d_out, int out_size)
{
    const float* features = (const float*)d_in[0];
    const float* weight   = (const float*)d_in[1];
    const int*   nodes    = (const int*)d_in[2];
    const int*   neigh    = (const int*)d_in[3];
    float*       out      = (float*)d_out;

    const int batch = in_sizes[2];      // 4096 (nodes element count)
    encoder_kernel<<<batch, 128>>>(features, weight, nodes, neigh, out);
}

// round 12
// speedup vs baseline: 1.0555x; 1.0183x over previous
#include <cuda_runtime.h>

// Encoder: out[b,e] = relu( sum_i combined[b,i] * weight[b,i,e] )
// combined = [ features[nodes[b]] , mean_j features[neigh_idx[b,j]] ]  (256 dims)
// Shapes: features [100000,128] f32, weight [4096,256,128] f32,
//         nodes [4096] i32, neigh_idx [4096,10] i32, out [4096,128] f32.
//
// CHAMPION (R6 configuration, 84.0us): DRAM-bound streaming kernel at the
// measured ~6.4-6.5TB/s platform ceiling for this read mix (confirmed via a
// pure-stream split kernel, LDG.256 variant, and L2 eviction-policy tests —
// all neutral). Compulsory traffic ~533MB => ~83us floor at achieved BW.
//  - warp-local gather: warp w builds exactly the comb slice it consumes, so
//    there is no block barrier between gather and stream (warps 0/1 start
//    streaming weight after a single self-feature row fetch).
//  - weight streamed with __ldcs float4 rows (512B/warp/request, unroll 8,
//    dual accumulators => 8 loads in flight per warp).
//  - 48 regs, 10 CTAs/SM (occ ~60%).

#define FEAT 128
#define EMBED 128
#define TWO_FEAT 256
#define NUM_SAMPLE 10

__global__ __launch_bounds__(128, 10)
void encoder_kernel(const float* __restrict__ features,
                    const float* __restrict__ weight,
                    const int*   __restrict__ nodes,
                    const int*   __restrict__ neigh,
                    float*       __restrict__ out)
{
    __shared__ float comb[TWO_FEAT];
    __shared__ float part[4][EMBED];

    const int b = blockIdx.x;
    const int t = threadIdx.x;          // 0..127
    const int warp = t >> 5;
    const int lane = t & 31;

    // ---- Phase 1 (warp-local): warp w builds comb[64w .. 64w+64).
    //   warp 0 -> self dims [0,64)     warp 1 -> self dims [64,128)
    //   warp 2 -> mean dims [0,64)     warp 3 -> mean dims [64,128)
    // Each warp writes a float2 per lane (64 floats), then __syncwarp only.
    {
        const int dim0 = (warp & 1) * 64 + lane * 2;   // 2 contiguous dims per lane
        float2 v;
        if (warp < 2) {
            const int node = __ldg(&nodes[b]);
            v = *reinterpret_cast<const float2*>(&features[(size_t)node * FEAT + dim0]);
        } else {
            float sx = 0.0f, sy = 0.0f;
            #pragma unroll
            for (int j = 0; j < NUM_SAMPLE; ++j) {
                const int nb = __ldg(&neigh[b * NUM_SAMPLE + j]);
                const float2 f = *reinterpret_cast<const float2*>(
                    &features[(size_t)nb * FEAT + dim0]);
                sx += f.x; sy += f.y;
            }
            v.x = sx * (1.0f / NUM_SAMPLE);
            v.y = sy * (1.0f / NUM_SAMPLE);
        }
        *reinterpret_cast<float2*>(&comb[warp * 64 + lane * 2]) = v;
        __syncwarp();
    }

    // ---- Phase 2: per-sample matvec, streaming weight[b] (128 KB/CTA).
    // warp w handles rows [w*64, w*64+64) == exactly the comb slice it wrote.
    // lane covers e = 4*lane..4*lane+3. __ldcs: weight is single-use.
    const float4* __restrict__ Wb =
        reinterpret_cast<const float4*>(weight + (size_t)b * TWO_FEAT * EMBED);
    const int i0 = warp * 64;

    float4 accA = make_float4(0.f, 0.f, 0.f, 0.f);
    float4 accB = make_float4(0.f, 0.f, 0.f, 0.f);

    #pragma unroll 8
    for (int k = 0; k < 64; k += 2) {
        const float  cA = comb[i0 + k];
        const float  cB = comb[i0 + k + 1];
        const float4 wA = __ldcs(&Wb[(size_t)(i0 + k)     * (EMBED / 4) + lane]);
        const float4 wB = __ldcs(&Wb[(size_t)(i0 + k + 1) * (EMBED / 4) + lane]);
        accA.x = fmaf(cA, wA.x, accA.x); accA.y = fmaf(cA, wA.y, accA.y);
        accA.z = fmaf(cA, wA.z, accA.z); accA.w = fmaf(cA, wA.w, accA.w);
        accB.x = fmaf(cB, wB.x, accB.x); accB.y = fmaf(cB, wB.y, accB.y);
        accB.z = fmaf(cB, wB.z, accB.z); accB.w = fmaf(cB, wB.w, accB.w);
    }

    float4 acc;
    acc.x = accA.x + accB.x;
    acc.y = accA.y + accB.y;
    acc.z = accA.z + accB.z;
    acc.w = accA.w + accB.w;

    // stash per-warp partials
    reinterpret_cast<float4*>(&part[warp][0])[lane] = acc;
    __syncthreads();

    // ---- reduce 4 warps, relu, store (coalesced 512B)
    const float v = part[0][t] + part[1][t] + part[2][t] + part[3][t];
    out[(size_t)b * EMBED + t] = fmaxf(v, 0.0f);
}

extern "C" void kernel_launch(void* const* d_in, const int* in_sizes, int n_in,
                              void* d_out, int out_size)
{
    const float* features = (const float*)d_in[0];
    const float* weight   = (const float*)d_in[1];
    const int*   nodes    = (const int*)d_in[2];
    const int*   neigh    = (const int*)d_in[3];
    float*       out      = (float*)d_out;

    const int batch = in_sizes[2];      // 4096 (nodes element count)
    encoder_kernel<<<batch, 128>>>(features, weight, nodes, neigh, out);
}